// round 14
// baseline (speedup 1.0000x reference)
#include <cuda_runtime.h>
#include <cuda_fp16.h>
#include <math_constants.h>
#include <cstdint>

#define BATCH 8192
#define DIM   128
#define BM    128
#define BN    128
#define MARGIN_F 0.5f

#define MTILES 64
#define NPAIRS_SYM 2080                  // 64*65/2 upper-triangular tile pairs
#define GRID_G 148                       // persistent, 1 CTA/SM
#define NTHREADS 512                     // 16 warps: 4 (M) x 4 (N), warp tile 32x32

#define ROWP 272                         // smem pitch: 256B data + 16B pad (conflict-free LDSM)
#define TILE_SZ (128 * ROWP)             // 34816
#define SM_A    0
#define SM_BBUF(i) (TILE_SZ * (1 + (i))) // 3 B buffers
#define SM_META (4 * TILE_SZ)            // 139264; per buffer: nrm[128]f + lbl[128]i = 1024B
#define SM_TOTAL (SM_META + 3 * 1024)    // 142336

// ---- scratch (no allocations allowed) ----
__device__ float  g_norms[BATCH];
__device__ int    g_maxpos[BATCH];       // d^2 float bits (clamped >=0: int order == float order)
__device__ int    g_minneg[BATCH];
__device__ __half g_sp[BATCH * 128];     // fp16 embeddings, row-major
__device__ int    g_depart = 0;          // finalize election

// ================= helpers =================
__device__ __forceinline__ uint32_t smem_u32(const void* p) {
    uint32_t a;
    asm("{ .reg .u64 t; cvta.to.shared.u64 t, %1; cvt.u32.u64 %0, t; }" : "=r"(a) : "l"(p));
    return a;
}
__device__ __forceinline__ void cp16(uint32_t dst, const void* src) {
    asm volatile("cp.async.cg.shared.global [%0], [%1], 16;" :: "r"(dst), "l"(src));
}
#define CP_COMMIT() asm volatile("cp.async.commit_group;" ::: "memory")
#define CP_WAIT(n)  asm volatile("cp.async.wait_group %0;" :: "n"(n) : "memory")

#define LDSM4(r, addr) \
    asm volatile("ldmatrix.sync.aligned.m8n8.x4.shared.b16 {%0,%1,%2,%3}, [%4];" \
                 : "=r"((r)[0]), "=r"((r)[1]), "=r"((r)[2]), "=r"((r)[3]) : "r"(addr))

#define MMAF16(d, a, b) \
    asm volatile("mma.sync.aligned.m16n8k16.row.col.f32.f16.f16.f32 " \
                 "{%0,%1,%2,%3}, {%4,%5,%6,%7}, {%8,%9}, {%0,%1,%2,%3};" \
                 : "+f"((d)[0]), "+f"((d)[1]), "+f"((d)[2]), "+f"((d)[3]) \
                 : "r"((a)[0]), "r"((a)[1]), "r"((a)[2]), "r"((a)[3]), \
                   "r"((b)[0]), "r"((b)[1]))

// ---- kernel 1: norms + fp16 cast + init accumulators ----
__global__ void prep_kernel(const float* __restrict__ emb) {
    int row  = blockIdx.x * 8 + (threadIdx.x >> 5);
    int lane = threadIdx.x & 31;
    float4 v = reinterpret_cast<const float4*>(emb)[row * 32 + lane];
    float s = v.x * v.x + v.y * v.y + v.z * v.z + v.w * v.w;
    #pragma unroll
    for (int o = 16; o; o >>= 1) s += __shfl_xor_sync(0xffffffffu, s, o);
    if (lane == 0) {
        g_norms[row]  = s;
        g_maxpos[row] = 0xFF800000;  // -inf bits
        g_minneg[row] = 0x7F800000;  // +inf bits
    }
    __half2* dst = reinterpret_cast<__half2*>(g_sp + (size_t)row * 128);
    dst[lane * 2 + 0] = __half2(__float2half_rn(v.x), __float2half_rn(v.y));
    dst[lane * 2 + 1] = __half2(__float2half_rn(v.z), __float2half_rn(v.w));
}

// async-copy one [128 x 256B] fp16 tile into pitch-272 smem
__device__ __forceinline__ void load_tile_async(const char* __restrict__ src,
                                                uint32_t sdst, int tid) {
    #pragma unroll
    for (int i = tid; i < 2048; i += NTHREADS) {
        int row = i >> 4, ch = i & 15;
        cp16(sdst + row * ROWP + ch * 16, src + row * 256 + ch * 16);
    }
}

// ---- kernel 2: persistent symmetric fp16 GEMM + hardest-pos/neg + last-CTA finalize ----
__global__ __launch_bounds__(NTHREADS, 1)
void dist_kernel(const int* __restrict__ labels, float* __restrict__ out) {
    extern __shared__ char smem[];
    __shared__ int s_last;
    const uint32_t sbase = smem_u32(smem);
    const int tid   = threadIdx.x;
    const int warp  = tid >> 5;
    const int lane  = tid & 31;
    const int mwarp = warp & 3;          // 4 warps over M (32 rows each)
    const int nwarp = warp >> 2;         // 4 warps over N (32 cols each)

    const uint32_t aBase = sbase + SM_A +
        (uint32_t)(mwarp * 32 + (lane & 15)) * ROWP + ((lane >> 4) * 16);
    const uint32_t bRow  =
        (uint32_t)(nwarp * 32 + (lane & 7) + ((lane >> 4) & 1) * 8) * ROWP +
        (((lane >> 3) & 1) * 16);

    int p  = (int)(((long long)blockIdx.x       * NPAIRS_SYM) / GRID_G);
    int p1 = (int)(((long long)(blockIdx.x + 1) * NPAIRS_SYM) / GRID_G);

    int mt = 0, S = 0;                   // row decode: row mt starts at linear index S
    while (S + (MTILES - mt) <= p) { S += MTILES - mt; mt++; }

    while (p < p1) {
        const int rowEnd = S + (MTILES - mt);
        const int pend   = min(p1, rowEnd);
        const int m0     = mt * BM;
        const int ncnt   = pend - p;
        const int nfirst = mt + (p - S);

        __syncthreads();  // previous m-range fully done with all smem buffers

        float nrmA[4]; int lblA[4], mrowA[4];
        #pragma unroll
        for (int i = 0; i < 4; i++) {
            int rl = mwarp * 32 + ((i >> 1) * 16) + ((i & 1) * 8) + (lane >> 2);
            mrowA[i] = m0 + rl;
            nrmA[i]  = g_norms[mrowA[i]];
            lblA[i]  = labels[mrowA[i]];
        }
        float maxpos[4], minneg[4];
        #pragma unroll
        for (int i = 0; i < 4; i++) { maxpos[i] = -CUDART_INF_F; minneg[i] = CUDART_INF_F; }

        // prologue: A + B(first) in one cp.async group (buffer 0)
        load_tile_async((const char*)(g_sp + (size_t)m0 * 128), sbase + SM_A, tid);
        {
            const int n0 = nfirst * BN;
            load_tile_async((const char*)(g_sp + (size_t)n0 * 128), sbase + SM_BBUF(0), tid);
            if (tid < BN) {
                ((float*)(smem + SM_META))[tid]       = g_norms[n0 + tid];
                ((int*)  (smem + SM_META + 512))[tid] = labels[n0 + tid];
            }
        }
        CP_COMMIT();

        for (int t = 0; t < ncnt; t++) {
            const int ntile = nfirst + t;
            const int n0    = ntile * BN;
            const bool offd = (ntile != mt);
            const int rb    = t % 3;
            if (t + 1 < ncnt) {
                const int wb  = (t + 1) % 3;
                const int n0n = (ntile + 1) * BN;
                load_tile_async((const char*)(g_sp + (size_t)n0n * 128),
                                sbase + SM_BBUF(wb), tid);
                if (tid < BN) {
                    ((float*)(smem + SM_META + wb * 1024))[tid]       = g_norms[n0n + tid];
                    ((int*)  (smem + SM_META + wb * 1024 + 512))[tid] = labels[n0n + tid];
                }
                CP_COMMIT();
                CP_WAIT(1);
            } else {
                CP_WAIT(0);
            }
            __syncthreads();      // single barrier per tile: buf[rb] + meta visible

            // ---- 1-pass fp16 GEMM on 32x32 warp tile ----
            float acc[2][4][4];
            #pragma unroll
            for (int a = 0; a < 2; a++)
                #pragma unroll
                for (int b = 0; b < 4; b++)
                    #pragma unroll
                    for (int c = 0; c < 4; c++) acc[a][b][c] = 0.f;

            const uint32_t bBase = sbase + SM_BBUF(rb) + bRow;
            #pragma unroll
            for (int ks = 0; ks < 8; ks++) {
                uint32_t a0[4], a1[4], b[2][4];
                LDSM4(a0, aBase + ks * 32);
                LDSM4(a1, aBase + ks * 32 + 16 * ROWP);
                #pragma unroll
                for (int np = 0; np < 2; np++)
                    LDSM4(b[np], bBase + (uint32_t)(np * 16) * ROWP + ks * 32);
                #pragma unroll
                for (int nt = 0; nt < 4; nt++) {
                    uint32_t* bp = &b[nt >> 1][(nt & 1) * 2];
                    MMAF16(acc[0][nt], a0, bp);
                    MMAF16(acc[1][nt], a1, bp);
                }
            }

            // ---- branch-free fused epilogue in d^2 space ----
            // diagonal element contributes d2~0 to maxpos only (clamped >=0): can never
            // beat a real positive (d2 ~ O(100)); neg side excludes it via same-label.
            const float* nB = (const float*)(smem + SM_META + rb * 1024);
            const int*   lB = (const int*)  (smem + SM_META + rb * 1024 + 512);
            float cmax[8], cmin[8];
            #pragma unroll
            for (int k = 0; k < 8; k++) { cmax[k] = -CUDART_INF_F; cmin[k] = CUDART_INF_F; }
            #pragma unroll
            for (int mtl = 0; mtl < 2; mtl++)
                #pragma unroll
                for (int half = 0; half < 2; half++) {
                    const int i   = mtl * 2 + half;
                    const float nA = nrmA[i];
                    const int   lA = lblA[i];
                    #pragma unroll
                    for (int nt = 0; nt < 4; nt++) {
                        #pragma unroll
                        for (int cc = 0; cc < 2; cc++) {
                            int col = nwarp * 32 + nt * 8 + (lane & 3) * 2 + cc;
                            float dot = acc[mtl][nt][half * 2 + cc];
                            float d2  = fmaxf(fmaf(-2.f, dot, nA + nB[col]), 0.f);
                            bool same = (lA == lB[col]);
                            float tpos = same ? d2 : -CUDART_INF_F;
                            float tneg = same ? CUDART_INF_F : d2;
                            int k = nt * 2 + cc;
                            maxpos[i] = fmaxf(maxpos[i], tpos);
                            minneg[i] = fminf(minneg[i], tneg);
                            cmax[k]   = fmaxf(cmax[k],   tpos);
                            cmin[k]   = fminf(cmin[k],   tneg);
                        }
                    }
                }
            if (offd) {
                // reduce columns over the 8 row-groups (lanes differing in bits 2..4)
                #pragma unroll
                for (int k = 0; k < 8; k++) {
                    #pragma unroll
                    for (int o = 4; o <= 16; o <<= 1) {
                        cmax[k] = fmaxf(cmax[k], __shfl_xor_sync(0xffffffffu, cmax[k], o));
                        cmin[k] = fminf(cmin[k], __shfl_xor_sync(0xffffffffu, cmin[k], o));
                    }
                }
                // each lane flushes one column: digit g = lane>>2, quad q = lane&3
                const int g = lane >> 2, q = lane & 3;
                float vmax = cmax[0], vmin = cmin[0];
                #pragma unroll
                for (int k = 1; k < 8; k++) {
                    if (g == k) { vmax = cmax[k]; vmin = cmin[k]; }
                }
                const int col = nwarp * 32 + ((g >> 1) * 8) + q * 2 + (g & 1);
                atomicMax(&g_maxpos[n0 + col], __float_as_int(vmax));  // -inf bits = no-op
                atomicMin(&g_minneg[n0 + col], __float_as_int(vmin));  // +inf bits = no-op
            }
        }

        // row-side: reduce across the 4 lanes of each quad, then atomics
        #pragma unroll
        for (int i = 0; i < 4; i++) {
            #pragma unroll
            for (int o = 1; o <= 2; o <<= 1) {
                maxpos[i] = fmaxf(maxpos[i], __shfl_xor_sync(0xffffffffu, maxpos[i], o));
                minneg[i] = fminf(minneg[i], __shfl_xor_sync(0xffffffffu, minneg[i], o));
            }
        }
        if ((lane & 3) == 0) {
            #pragma unroll
            for (int i = 0; i < 4; i++) {
                atomicMax(&g_maxpos[mrowA[i]], __float_as_int(maxpos[i]));
                atomicMin(&g_minneg[mrowA[i]], __float_as_int(minneg[i]));
            }
        }
        p = pend;
        if (p == rowEnd) { S = rowEnd; mt++; }
    }

    // ---- last-CTA finalize (sqrt applied here; monotone) ----
    __syncthreads();
    if (tid == 0) {
        __threadfence();
        int d = atomicAdd(&g_depart, 1);
        s_last = (d == GRID_G - 1) ? 1 : 0;
    }
    __syncthreads();
    if (s_last) {
        __threadfence();   // acquire: see all CTAs' g_maxpos/g_minneg atomics
        float* ssum = (float*)smem;            // reuse smem
        float* scnt = (float*)smem + NTHREADS;
        float s = 0.f, c = 0.f;
        for (int i = tid; i < BATCH; i += NTHREADS) {
            int mp = g_maxpos[i], mn = g_minneg[i];
            bool valid = (mp != (int)0xFF800000) && (mn != 0x7F800000);
            float hp = sqrtf(fmaxf(__int_as_float(mp), 0.f));
            float hn = sqrtf(fmaxf(__int_as_float(mn), 0.f));
            float per = fmaxf(hp - hn + MARGIN_F, 0.f);
            if (valid) { s += per; c += 1.f; }
        }
        ssum[tid] = s; scnt[tid] = c;
        __syncthreads();
        for (int st = NTHREADS / 2; st; st >>= 1) {
            if (tid < st) { ssum[tid] += ssum[tid + st]; scnt[tid] += scnt[tid + st]; }
            __syncthreads();
        }
        if (tid == 0) {
            out[0] = ssum[0] / fmaxf(scnt[0], 1.f);
            atomicExch(&g_depart, 0);   // reset for next graph replay
            __threadfence();
        }
    }
}

extern "C" void kernel_launch(void* const* d_in, const int* in_sizes, int n_in,
                              void* d_out, int out_size) {
    const float* emb = (const float*)d_in[0];
    const int*   lbl = (const int*)d_in[1];   // jax int64 -> int32 (no x64)
    (void)in_sizes; (void)n_in; (void)out_size;

    cudaFuncSetAttribute(dist_kernel, cudaFuncAttributeMaxDynamicSharedMemorySize, SM_TOTAL);

    prep_kernel<<<BATCH / 8, 256>>>(emb);
    dist_kernel<<<GRID_G, NTHREADS, SM_TOTAL>>>(lbl, (float*)d_out);
}

// round 15
// speedup vs baseline: 1.0623x; 1.0623x over previous
#include <cuda_runtime.h>
#include <cuda_fp16.h>
#include <math_constants.h>
#include <cstdint>

#define BATCH 8192
#define DIM   128
#define BM    128
#define BN    128
#define MARGIN_F 0.5f

#define MTILES 64
#define NPAIRS_SYM 2080                  // 64*65/2 upper-triangular tile pairs
#define GRID_G 296                       // persistent, 2 CTAs/SM
#define NTHREADS 256                     // 8 warps: 4 (M) x 2 (N), warp tile 32x64

#define ROWP 272                         // smem pitch: 256B data + 16B pad (conflict-free LDSM)
#define TILE_SZ (128 * ROWP)             // 34816
#define SM_A    0
#define SM_BBUF(i) (TILE_SZ * (1 + (i))) // 2 B buffers
#define SM_META (3 * TILE_SZ)            // 104448; per buffer: nrm[128]f + lbl[128]i = 1024B
#define SM_TOTAL (SM_META + 2 * 1024)    // 106496 (x2 CTAs = 208KB <= 228KB)

// ---- scratch (no allocations allowed) ----
__device__ float  g_norms[BATCH];
__device__ int    g_maxpos[BATCH];       // d^2 float bits (clamped >=0: int order == float order)
__device__ int    g_minneg[BATCH];
__device__ __half g_sp[BATCH * 128];     // fp16 embeddings, row-major

// ================= helpers =================
__device__ __forceinline__ uint32_t smem_u32(const void* p) {
    uint32_t a;
    asm("{ .reg .u64 t; cvta.to.shared.u64 t, %1; cvt.u32.u64 %0, t; }" : "=r"(a) : "l"(p));
    return a;
}
__device__ __forceinline__ void cp16(uint32_t dst, const void* src) {
    asm volatile("cp.async.cg.shared.global [%0], [%1], 16;" :: "r"(dst), "l"(src));
}
#define CP_COMMIT() asm volatile("cp.async.commit_group;" ::: "memory")
#define CP_WAIT(n)  asm volatile("cp.async.wait_group %0;" :: "n"(n) : "memory")

#define LDSM4(r, addr) \
    asm volatile("ldmatrix.sync.aligned.m8n8.x4.shared.b16 {%0,%1,%2,%3}, [%4];" \
                 : "=r"((r)[0]), "=r"((r)[1]), "=r"((r)[2]), "=r"((r)[3]) : "r"(addr))

#define MMAF16(d, a, b) \
    asm volatile("mma.sync.aligned.m16n8k16.row.col.f32.f16.f16.f32 " \
                 "{%0,%1,%2,%3}, {%4,%5,%6,%7}, {%8,%9}, {%0,%1,%2,%3};" \
                 : "+f"((d)[0]), "+f"((d)[1]), "+f"((d)[2]), "+f"((d)[3]) \
                 : "r"((a)[0]), "r"((a)[1]), "r"((a)[2]), "r"((a)[3]), \
                   "r"((b)[0]), "r"((b)[1]))

// ---- kernel 1: norms + fp16 cast + init accumulators ----
__global__ void prep_kernel(const float* __restrict__ emb) {
    int row  = blockIdx.x * 8 + (threadIdx.x >> 5);
    int lane = threadIdx.x & 31;
    float4 v = reinterpret_cast<const float4*>(emb)[row * 32 + lane];
    float s = v.x * v.x + v.y * v.y + v.z * v.z + v.w * v.w;
    #pragma unroll
    for (int o = 16; o; o >>= 1) s += __shfl_xor_sync(0xffffffffu, s, o);
    if (lane == 0) {
        g_norms[row]  = s;
        g_maxpos[row] = 0xFF800000;  // -inf bits
        g_minneg[row] = 0x7F800000;  // +inf bits
    }
    __half2* dst = reinterpret_cast<__half2*>(g_sp + (size_t)row * 128);
    dst[lane * 2 + 0] = __half2(__float2half_rn(v.x), __float2half_rn(v.y));
    dst[lane * 2 + 1] = __half2(__float2half_rn(v.z), __float2half_rn(v.w));
}

// async-copy one [128 x 256B] fp16 tile into pitch-272 smem
__device__ __forceinline__ void load_tile_async(const char* __restrict__ src,
                                                uint32_t sdst, int tid) {
    #pragma unroll
    for (int i = tid; i < 2048; i += NTHREADS) {
        int row = i >> 3, ch = i & 7;            // 256 thr: 8 chunks/row... (2048 = 128*16)
        (void)row; (void)ch;
        break;
    }
    // 128 rows x 16 chunks of 16B = 2048 chunks; 256 threads -> 8 iters
    #pragma unroll
    for (int i = tid; i < 2048; i += NTHREADS) {
        int row = i >> 4, ch = i & 15;
        cp16(sdst + row * ROWP + ch * 16, src + row * 256 + ch * 16);
    }
}

// ---- kernel 2: persistent symmetric fp16 GEMM + fused hardest-pos/neg (d^2) ----
// 2 CTAs/SM x 256 thr; double-buffered B with a single barrier per tile
// (prefetch issued AFTER the barrier, so the barrier proves the target drained)
__global__ __launch_bounds__(NTHREADS, 2)
void dist_kernel(const int* __restrict__ labels) {
    extern __shared__ char smem[];
    const uint32_t sbase = smem_u32(smem);
    const int tid   = threadIdx.x;
    const int warp  = tid >> 5;
    const int lane  = tid & 31;
    const int mwarp = warp & 3;          // 4 warps over M (32 rows each)
    const int nwarp = warp >> 2;         // 2 warps over N (64 cols each)

    const uint32_t aBase = sbase + SM_A +
        (uint32_t)(mwarp * 32 + (lane & 15)) * ROWP + ((lane >> 4) * 16);
    const uint32_t bRow  =
        (uint32_t)(nwarp * 64 + (lane & 7) + ((lane >> 4) & 1) * 8) * ROWP +
        (((lane >> 3) & 1) * 16);

    int p  = (int)(((long long)blockIdx.x       * NPAIRS_SYM) / GRID_G);
    int p1 = (int)(((long long)(blockIdx.x + 1) * NPAIRS_SYM) / GRID_G);

    int mt = 0, S = 0;                   // row decode: row mt starts at linear index S
    while (S + (MTILES - mt) <= p) { S += MTILES - mt; mt++; }

    while (p < p1) {
        const int rowEnd = S + (MTILES - mt);
        const int pend   = min(p1, rowEnd);
        const int m0     = mt * BM;
        const int ncnt   = pend - p;
        const int nfirst = mt + (p - S);

        __syncthreads();  // previous m-range fully done with all smem buffers

        float nrmA[4]; int lblA[4], mrowA[4];
        #pragma unroll
        for (int i = 0; i < 4; i++) {
            int rl = mwarp * 32 + ((i >> 1) * 16) + ((i & 1) * 8) + (lane >> 2);
            mrowA[i] = m0 + rl;
            nrmA[i]  = g_norms[mrowA[i]];
            lblA[i]  = labels[mrowA[i]];
        }
        float maxpos[4], minneg[4];
        #pragma unroll
        for (int i = 0; i < 4; i++) { maxpos[i] = -CUDART_INF_F; minneg[i] = CUDART_INF_F; }

        // prologue: A + B(first) in one cp.async group (buffer 0)
        load_tile_async((const char*)(g_sp + (size_t)m0 * 128), sbase + SM_A, tid);
        {
            const int n0 = nfirst * BN;
            load_tile_async((const char*)(g_sp + (size_t)n0 * 128), sbase + SM_BBUF(0), tid);
            if (tid < BN) {
                ((float*)(smem + SM_META))[tid]       = g_norms[n0 + tid];
                ((int*)  (smem + SM_META + 512))[tid] = labels[n0 + tid];
            }
        }
        CP_COMMIT();

        for (int t = 0; t < ncnt; t++) {
            const int ntile = nfirst + t;
            const int n0    = ntile * BN;
            const bool offd = (ntile != mt);
            const int rb    = t & 1;

            CP_WAIT(0);           // tile t data (and A on t=0) landed
            __syncthreads();      // data visible to all; buf[rb^1] (tile t-1) drained

            if (t + 1 < ncnt) {   // prefetch AFTER the barrier -> write target is safe
                const int wb  = rb ^ 1;
                const int n0n = (ntile + 1) * BN;
                load_tile_async((const char*)(g_sp + (size_t)n0n * 128),
                                sbase + SM_BBUF(wb), tid);
                if (tid < BN) {
                    ((float*)(smem + SM_META + wb * 1024))[tid]       = g_norms[n0n + tid];
                    ((int*)  (smem + SM_META + wb * 1024 + 512))[tid] = labels[n0n + tid];
                }
                CP_COMMIT();
            }

            // ---- 1-pass fp16 GEMM on 32x64 warp tile ----
            float acc[2][8][4];
            #pragma unroll
            for (int a = 0; a < 2; a++)
                #pragma unroll
                for (int b = 0; b < 8; b++)
                    #pragma unroll
                    for (int c = 0; c < 4; c++) acc[a][b][c] = 0.f;

            const uint32_t bBase = sbase + SM_BBUF(rb) + bRow;
            #pragma unroll
            for (int ks = 0; ks < 8; ks++) {
                uint32_t a0[4], a1[4], b[4][4];
                LDSM4(a0, aBase + ks * 32);
                LDSM4(a1, aBase + ks * 32 + 16 * ROWP);
                #pragma unroll
                for (int np = 0; np < 4; np++)
                    LDSM4(b[np], bBase + (uint32_t)(np * 16) * ROWP + ks * 32);
                #pragma unroll
                for (int nt = 0; nt < 8; nt++) {
                    uint32_t* bp = &b[nt >> 1][(nt & 1) * 2];
                    MMAF16(acc[0][nt], a0, bp);
                    MMAF16(acc[1][nt], a1, bp);
                }
            }

            // ---- fused epilogue in d^2 space: row-side always, col-side if off-diagonal ----
            const float* nB = (const float*)(smem + SM_META + rb * 1024);
            const int*   lB = (const int*)  (smem + SM_META + rb * 1024 + 512);
            float cmax[16], cmin[16];
            #pragma unroll
            for (int k = 0; k < 16; k++) { cmax[k] = -CUDART_INF_F; cmin[k] = CUDART_INF_F; }
            #pragma unroll
            for (int mtl = 0; mtl < 2; mtl++)
                #pragma unroll
                for (int half = 0; half < 2; half++) {
                    const int i   = mtl * 2 + half;
                    const float nA = nrmA[i];
                    const int   lA = lblA[i];
                    const int   mr = mrowA[i];
                    #pragma unroll
                    for (int nt = 0; nt < 8; nt++) {
                        #pragma unroll
                        for (int cc = 0; cc < 2; cc++) {
                            int col = nwarp * 64 + nt * 8 + (lane & 3) * 2 + cc;
                            float dot = acc[mtl][nt][half * 2 + cc];
                            float d2  = fmaxf(fmaf(-2.f, dot, nA + nB[col]), 0.f);
                            bool same = (lA == lB[col]);
                            if (mr != n0 + col) {
                                if (same) maxpos[i] = fmaxf(maxpos[i], d2);
                                else      minneg[i] = fminf(minneg[i], d2);
                            }
                            if (offd) {
                                int k = nt * 2 + cc;
                                if (same) cmax[k] = fmaxf(cmax[k], d2);
                                else      cmin[k] = fminf(cmin[k], d2);
                            }
                        }
                    }
                }
            if (offd) {
                // reduce columns over the 8 row-groups (lanes differing in bits 2..4)
                #pragma unroll
                for (int k = 0; k < 16; k++) {
                    #pragma unroll
                    for (int o = 4; o <= 16; o <<= 1) {
                        cmax[k] = fmaxf(cmax[k], __shfl_xor_sync(0xffffffffu, cmax[k], o));
                        cmin[k] = fminf(cmin[k], __shfl_xor_sync(0xffffffffu, cmin[k], o));
                    }
                }
                // each lane flushes two columns: digits g and g+8 (g = lane>>2), quad q
                const int g = lane >> 2, q = lane & 3;
                float vmax0 = cmax[0], vmin0 = cmin[0];
                float vmax1 = cmax[8], vmin1 = cmin[8];
                #pragma unroll
                for (int k = 1; k < 8; k++) {
                    if (g == k) {
                        vmax0 = cmax[k];     vmin0 = cmin[k];
                        vmax1 = cmax[k + 8]; vmin1 = cmin[k + 8];
                    }
                }
                const int col0 = nwarp * 64 + ((g >> 1) * 8) + q * 2 + (g & 1);
                const int col1 = nwarp * 64 + (((g + 8) >> 1) * 8) + q * 2 + ((g + 8) & 1);
                atomicMax(&g_maxpos[n0 + col0], __float_as_int(vmax0));
                atomicMin(&g_minneg[n0 + col0], __float_as_int(vmin0));
                atomicMax(&g_maxpos[n0 + col1], __float_as_int(vmax1));
                atomicMin(&g_minneg[n0 + col1], __float_as_int(vmin1));
            }
        }

        // row-side: reduce across the 4 lanes of each quad, then atomics
        #pragma unroll
        for (int i = 0; i < 4; i++) {
            #pragma unroll
            for (int o = 1; o <= 2; o <<= 1) {
                maxpos[i] = fmaxf(maxpos[i], __shfl_xor_sync(0xffffffffu, maxpos[i], o));
                minneg[i] = fminf(minneg[i], __shfl_xor_sync(0xffffffffu, minneg[i], o));
            }
        }
        if ((lane & 3) == 0) {
            #pragma unroll
            for (int i = 0; i < 4; i++) {
                atomicMax(&g_maxpos[mrowA[i]], __float_as_int(maxpos[i]));
                atomicMin(&g_minneg[mrowA[i]], __float_as_int(minneg[i]));
            }
        }
        p = pend;
        if (p == rowEnd) { S = rowEnd; mt++; }
    }
}

// ---- kernel 3: single-block finalize (sqrt applied here; monotone) ----
__global__ __launch_bounds__(1024)
void finalize_kernel(float* __restrict__ out) {
    __shared__ float ssum[1024], scnt[1024];
    float s = 0.f, c = 0.f;
    for (int i = threadIdx.x; i < BATCH; i += 1024) {
        int mp = g_maxpos[i], mn = g_minneg[i];
        bool valid = (mp != (int)0xFF800000) && (mn != 0x7F800000);
        float hp = sqrtf(fmaxf(__int_as_float(mp), 0.f));
        float hn = sqrtf(fmaxf(__int_as_float(mn), 0.f));
        float per = fmaxf(hp - hn + MARGIN_F, 0.f);
        if (valid) { s += per; c += 1.f; }
    }
    ssum[threadIdx.x] = s; scnt[threadIdx.x] = c;
    __syncthreads();
    for (int st = 512; st; st >>= 1) {
        if (threadIdx.x < st) {
            ssum[threadIdx.x] += ssum[threadIdx.x + st];
            scnt[threadIdx.x] += scnt[threadIdx.x + st];
        }
        __syncthreads();
    }
    if (threadIdx.x == 0) out[0] = ssum[0] / fmaxf(scnt[0], 1.f);
}

extern "C" void kernel_launch(void* const* d_in, const int* in_sizes, int n_in,
                              void* d_out, int out_size) {
    const float* emb = (const float*)d_in[0];
    const int*   lbl = (const int*)d_in[1];   // jax int64 -> int32 (no x64)
    (void)in_sizes; (void)n_in; (void)out_size;

    cudaFuncSetAttribute(dist_kernel, cudaFuncAttributeMaxDynamicSharedMemorySize, SM_TOTAL);

    prep_kernel<<<BATCH / 8, 256>>>(emb);
    dist_kernel<<<GRID_G, NTHREADS, SM_TOTAL>>>(lbl);
    finalize_kernel<<<1, 1024>>>((float*)d_out);
}

// round 16
// speedup vs baseline: 1.0965x; 1.0322x over previous
#include <cuda_runtime.h>
#include <cuda_fp16.h>
#include <math_constants.h>
#include <cstdint>

#define BATCH 8192
#define DIM   128
#define BM    128
#define BN    128
#define MARGIN_F 0.5f

#define MTILES 64
#define NPAIRS_SYM 2080                  // 64*65/2 upper-triangular tile pairs
#define GRID_G 296                       // persistent, 2 CTAs/SM
#define NTHREADS 256                     // 8 warps: 4 (M) x 2 (N), warp tile 32x64

#define ROWP 272                         // smem pitch: 256B data + 16B pad (conflict-free LDSM)
#define TILE_SZ (128 * ROWP)             // 34816
#define SM_A    0
#define SM_BBUF(i) (TILE_SZ * (1 + (i))) // 2 B buffers
#define SM_META (3 * TILE_SZ)            // 104448; per buffer: nrm[128]f + lbl[128]i = 1024B
#define SM_TOTAL (SM_META + 2 * 1024)    // 106496 (x2 CTAs = 208KB <= 228KB)

// ---- scratch (no allocations allowed) ----
__device__ float  g_norms[BATCH];
__device__ int    g_maxpos[BATCH];       // d^2 float bits (clamped >=0: int order == float order)
__device__ int    g_minneg[BATCH];
__device__ __half g_sp[BATCH * 128];     // fp16 embeddings, row-major

// ================= helpers =================
__device__ __forceinline__ uint32_t smem_u32(const void* p) {
    uint32_t a;
    asm("{ .reg .u64 t; cvta.to.shared.u64 t, %1; cvt.u32.u64 %0, t; }" : "=r"(a) : "l"(p));
    return a;
}
__device__ __forceinline__ void cp16(uint32_t dst, const void* src) {
    asm volatile("cp.async.cg.shared.global [%0], [%1], 16;" :: "r"(dst), "l"(src));
}
#define CP_COMMIT() asm volatile("cp.async.commit_group;" ::: "memory")
#define CP_WAIT(n)  asm volatile("cp.async.wait_group %0;" :: "n"(n) : "memory")

#define LDSM4(r, addr) \
    asm volatile("ldmatrix.sync.aligned.m8n8.x4.shared.b16 {%0,%1,%2,%3}, [%4];" \
                 : "=r"((r)[0]), "=r"((r)[1]), "=r"((r)[2]), "=r"((r)[3]) : "r"(addr))

#define MMAF16(d, a, b) \
    asm volatile("mma.sync.aligned.m16n8k16.row.col.f32.f16.f16.f32 " \
                 "{%0,%1,%2,%3}, {%4,%5,%6,%7}, {%8,%9}, {%0,%1,%2,%3};" \
                 : "+f"((d)[0]), "+f"((d)[1]), "+f"((d)[2]), "+f"((d)[3]) \
                 : "r"((a)[0]), "r"((a)[1]), "r"((a)[2]), "r"((a)[3]), \
                   "r"((b)[0]), "r"((b)[1]))

// ---- kernel 1: norms + fp16 cast + init accumulators ----
__global__ void prep_kernel(const float* __restrict__ emb) {
    int row  = blockIdx.x * 8 + (threadIdx.x >> 5);
    int lane = threadIdx.x & 31;
    float4 v = reinterpret_cast<const float4*>(emb)[row * 32 + lane];
    float s = v.x * v.x + v.y * v.y + v.z * v.z + v.w * v.w;
    #pragma unroll
    for (int o = 16; o; o >>= 1) s += __shfl_xor_sync(0xffffffffu, s, o);
    if (lane == 0) {
        g_norms[row]  = s;
        g_maxpos[row] = 0xFF800000;  // -inf bits
        g_minneg[row] = 0x7F800000;  // +inf bits
    }
    __half2* dst = reinterpret_cast<__half2*>(g_sp + (size_t)row * 128);
    dst[lane * 2 + 0] = __half2(__float2half_rn(v.x), __float2half_rn(v.y));
    dst[lane * 2 + 1] = __half2(__float2half_rn(v.z), __float2half_rn(v.w));
}

// async-copy one [128 x 256B] fp16 tile into pitch-272 smem
__device__ __forceinline__ void load_tile_async(const char* __restrict__ src,
                                                uint32_t sdst, int tid) {
    #pragma unroll
    for (int i = tid; i < 2048; i += NTHREADS) {
        int row = i >> 4, ch = i & 15;
        cp16(sdst + row * ROWP + ch * 16, src + row * 256 + ch * 16);
    }
}

// ---- kernel 2: persistent symmetric fp16 GEMM + fused hardest-pos/neg (d^2) ----
// 2 CTAs/SM; half-split k-loop with double-buffered fragments (software pipelining)
__global__ __launch_bounds__(NTHREADS, 2)
void dist_kernel(const int* __restrict__ labels) {
    extern __shared__ char smem[];
    const uint32_t sbase = smem_u32(smem);
    const int tid   = threadIdx.x;
    const int warp  = tid >> 5;
    const int lane  = tid & 31;
    const int mwarp = warp & 3;          // 4 warps over M (32 rows each)
    const int nwarp = warp >> 2;         // 2 warps over N (64 cols each)

    const uint32_t aBase = sbase + SM_A +
        (uint32_t)(mwarp * 32 + (lane & 15)) * ROWP + ((lane >> 4) * 16);
    const uint32_t bRow  =
        (uint32_t)(nwarp * 64 + (lane & 7) + ((lane >> 4) & 1) * 8) * ROWP +
        (((lane >> 3) & 1) * 16);

    int p  = (int)(((long long)blockIdx.x       * NPAIRS_SYM) / GRID_G);
    int p1 = (int)(((long long)(blockIdx.x + 1) * NPAIRS_SYM) / GRID_G);

    int mt = 0, S = 0;                   // row decode: row mt starts at linear index S
    while (S + (MTILES - mt) <= p) { S += MTILES - mt; mt++; }

    while (p < p1) {
        const int rowEnd = S + (MTILES - mt);
        const int pend   = min(p1, rowEnd);
        const int m0     = mt * BM;
        const int ncnt   = pend - p;
        const int nfirst = mt + (p - S);

        __syncthreads();  // previous m-range fully done with all smem buffers

        float nrmA[4]; int lblA[4], mrowA[4];
        #pragma unroll
        for (int i = 0; i < 4; i++) {
            int rl = mwarp * 32 + ((i >> 1) * 16) + ((i & 1) * 8) + (lane >> 2);
            mrowA[i] = m0 + rl;
            nrmA[i]  = g_norms[mrowA[i]];
            lblA[i]  = labels[mrowA[i]];
        }
        float maxpos[4], minneg[4];
        #pragma unroll
        for (int i = 0; i < 4; i++) { maxpos[i] = -CUDART_INF_F; minneg[i] = CUDART_INF_F; }

        // prologue: A + B(first) in one cp.async group (buffer 0)
        load_tile_async((const char*)(g_sp + (size_t)m0 * 128), sbase + SM_A, tid);
        {
            const int n0 = nfirst * BN;
            load_tile_async((const char*)(g_sp + (size_t)n0 * 128), sbase + SM_BBUF(0), tid);
            if (tid < BN) {
                ((float*)(smem + SM_META))[tid]       = g_norms[n0 + tid];
                ((int*)  (smem + SM_META + 512))[tid] = labels[n0 + tid];
            }
        }
        CP_COMMIT();

        for (int t = 0; t < ncnt; t++) {
            const int ntile = nfirst + t;
            const int n0    = ntile * BN;
            const bool offd = (ntile != mt);
            const int rb    = t & 1;

            CP_WAIT(0);           // tile t data (and A on t=0) landed
            __syncthreads();      // data visible; buf[rb^1] (tile t-1) drained

            if (t + 1 < ncnt) {   // prefetch AFTER the barrier -> write target is safe
                const int wb  = rb ^ 1;
                const int n0n = (ntile + 1) * BN;
                load_tile_async((const char*)(g_sp + (size_t)n0n * 128),
                                sbase + SM_BBUF(wb), tid);
                if (tid < BN) {
                    ((float*)(smem + SM_META + wb * 1024))[tid]       = g_norms[n0n + tid];
                    ((int*)  (smem + SM_META + wb * 1024 + 512))[tid] = labels[n0n + tid];
                }
                CP_COMMIT();
            }

            const float* nB = (const float*)(smem + SM_META + rb * 1024);
            const int*   lB = (const int*)  (smem + SM_META + rb * 1024 + 512);

            // ---- two 32x32 column halves, each with a pipelined k-loop + epilogue ----
            #pragma unroll
            for (int half = 0; half < 2; half++) {
                const uint32_t bBase = sbase + SM_BBUF(rb) + bRow +
                                       (uint32_t)(half * 32) * ROWP;
                float acc[2][4][4];
                #pragma unroll
                for (int a = 0; a < 2; a++)
                    #pragma unroll
                    for (int b = 0; b < 4; b++)
                        #pragma unroll
                        for (int c = 0; c < 4; c++) acc[a][b][c] = 0.f;

                uint32_t af[2][2][4], bf[2][2][4];
                LDSM4(af[0][0], aBase);
                LDSM4(af[0][1], aBase + 16 * ROWP);
                LDSM4(bf[0][0], bBase);
                LDSM4(bf[0][1], bBase + 16 * ROWP);
                #pragma unroll
                for (int ks = 0; ks < 8; ks++) {
                    const int cur = ks & 1, nxt = cur ^ 1;
                    if (ks < 7) {   // prefetch ks+1 fragments before issuing MMAs
                        LDSM4(af[nxt][0], aBase + (ks + 1) * 32);
                        LDSM4(af[nxt][1], aBase + (ks + 1) * 32 + 16 * ROWP);
                        LDSM4(bf[nxt][0], bBase + (ks + 1) * 32);
                        LDSM4(bf[nxt][1], bBase + (ks + 1) * 32 + 16 * ROWP);
                    }
                    #pragma unroll
                    for (int nt = 0; nt < 4; nt++) {
                        uint32_t* bp = &bf[cur][nt >> 1][(nt & 1) * 2];
                        MMAF16(acc[0][nt], af[cur][0], bp);
                        MMAF16(acc[1][nt], af[cur][1], bp);
                    }
                }

                // ---- epilogue for this half in d^2 space ----
                float cmax[8], cmin[8];
                #pragma unroll
                for (int k = 0; k < 8; k++) { cmax[k] = -CUDART_INF_F; cmin[k] = CUDART_INF_F; }
                #pragma unroll
                for (int mtl = 0; mtl < 2; mtl++)
                    #pragma unroll
                    for (int hh = 0; hh < 2; hh++) {
                        const int i   = mtl * 2 + hh;
                        const float nA = nrmA[i];
                        const int   lA = lblA[i];
                        const int   mr = mrowA[i];
                        #pragma unroll
                        for (int nt = 0; nt < 4; nt++) {
                            #pragma unroll
                            for (int cc = 0; cc < 2; cc++) {
                                int col = nwarp * 64 + half * 32 + nt * 8 +
                                          (lane & 3) * 2 + cc;
                                float dot = acc[mtl][nt][hh * 2 + cc];
                                float d2  = fmaxf(fmaf(-2.f, dot, nA + nB[col]), 0.f);
                                bool same = (lA == lB[col]);
                                if (mr != n0 + col) {
                                    if (same) maxpos[i] = fmaxf(maxpos[i], d2);
                                    else      minneg[i] = fminf(minneg[i], d2);
                                }
                                if (offd) {
                                    int k = nt * 2 + cc;
                                    if (same) cmax[k] = fmaxf(cmax[k], d2);
                                    else      cmin[k] = fminf(cmin[k], d2);
                                }
                            }
                        }
                    }
                if (offd) {
                    // reduce columns over the 8 row-groups (lanes differing in bits 2..4)
                    #pragma unroll
                    for (int k = 0; k < 8; k++) {
                        #pragma unroll
                        for (int o = 4; o <= 16; o <<= 1) {
                            cmax[k] = fmaxf(cmax[k], __shfl_xor_sync(0xffffffffu, cmax[k], o));
                            cmin[k] = fminf(cmin[k], __shfl_xor_sync(0xffffffffu, cmin[k], o));
                        }
                    }
                    // each lane flushes one column: digit g = lane>>2, quad q = lane&3
                    const int g = lane >> 2, q = lane & 3;
                    float vmax = cmax[0], vmin = cmin[0];
                    #pragma unroll
                    for (int k = 1; k < 8; k++) {
                        if (g == k) { vmax = cmax[k]; vmin = cmin[k]; }
                    }
                    const int col = nwarp * 64 + half * 32 + ((g >> 1) * 8) + q * 2 + (g & 1);
                    atomicMax(&g_maxpos[n0 + col], __float_as_int(vmax));  // -inf: no-op
                    atomicMin(&g_minneg[n0 + col], __float_as_int(vmin));  // +inf: no-op
                }
            }
        }

        // row-side: reduce across the 4 lanes of each quad, then atomics
        #pragma unroll
        for (int i = 0; i < 4; i++) {
            #pragma unroll
            for (int o = 1; o <= 2; o <<= 1) {
                maxpos[i] = fmaxf(maxpos[i], __shfl_xor_sync(0xffffffffu, maxpos[i], o));
                minneg[i] = fminf(minneg[i], __shfl_xor_sync(0xffffffffu, minneg[i], o));
            }
        }
        if ((lane & 3) == 0) {
            #pragma unroll
            for (int i = 0; i < 4; i++) {
                atomicMax(&g_maxpos[mrowA[i]], __float_as_int(maxpos[i]));
                atomicMin(&g_minneg[mrowA[i]], __float_as_int(minneg[i]));
            }
        }
        p = pend;
        if (p == rowEnd) { S = rowEnd; mt++; }
    }
}

// ---- kernel 3: single-block finalize (sqrt applied here; monotone) ----
__global__ __launch_bounds__(1024)
void finalize_kernel(float* __restrict__ out) {
    __shared__ float ssum[1024], scnt[1024];
    float s = 0.f, c = 0.f;
    for (int i = threadIdx.x; i < BATCH; i += 1024) {
        int mp = g_maxpos[i], mn = g_minneg[i];
        bool valid = (mp != (int)0xFF800000) && (mn != 0x7F800000);
        float hp = sqrtf(fmaxf(__int_as_float(mp), 0.f));
        float hn = sqrtf(fmaxf(__int_as_float(mn), 0.f));
        float per = fmaxf(hp - hn + MARGIN_F, 0.f);
        if (valid) { s += per; c += 1.f; }
    }
    ssum[threadIdx.x] = s; scnt[threadIdx.x] = c;
    __syncthreads();
    for (int st = 512; st; st >>= 1) {
        if (threadIdx.x < st) {
            ssum[threadIdx.x] += ssum[threadIdx.x + st];
            scnt[threadIdx.x] += scnt[threadIdx.x + st];
        }
        __syncthreads();
    }
    if (threadIdx.x == 0) out[0] = ssum[0] / fmaxf(scnt[0], 1.f);
}

extern "C" void kernel_launch(void* const* d_in, const int* in_sizes, int n_in,
                              void* d_out, int out_size) {
    const float* emb = (const float*)d_in[0];
    const int*   lbl = (const int*)d_in[1];   // jax int64 -> int32 (no x64)
    (void)in_sizes; (void)n_in; (void)out_size;

    cudaFuncSetAttribute(dist_kernel, cudaFuncAttributeMaxDynamicSharedMemorySize, SM_TOTAL);

    prep_kernel<<<BATCH / 8, 256>>>(emb);
    dist_kernel<<<GRID_G, NTHREADS, SM_TOTAL>>>(lbl);
    finalize_kernel<<<1, 1024>>>((float*)d_out);
}